// round 5
// baseline (speedup 1.0000x reference)
#include <cuda_runtime.h>
#include <math.h>

// B=32, T=512, F=1280, H=512, L=3. 3H=1536, 2H=1024. M=B*T=16384.
//
// Per layer l:
//   gemm_xg : xg[dir][t*32+b][1536] = in[b*512+t][:] . w_ih[dir*1536+g][:] + b_ih
//   gru_rec : persistent, 128 CTAs (64/dir), 512 steps with grid barrier
//   bn_zero/bn_stats/bn_finalize : training-mode BN stats -> scale/shift
//   bn_apply: y -> normalized [B][T][2H] into g_xin (or d_out for last layer)

#define XG_DIR 25165824   // 512*32*1536
#define Y_DIR   8388608   // 512*32*512

// ---------------- scratch (device globals; no allocation allowed) ----------
__device__ float g_xg[2 * XG_DIR];        // 201 MB
__device__ float g_y [2 * Y_DIR];         //  67 MB
__device__ float g_xin[32 * 512 * 1024];  //  67 MB
__device__ float g_scale[1024];
__device__ float g_shift[1024];
__device__ float g_sum[1024];
__device__ float g_sqs[1024];
__device__ unsigned g_cnt;
__device__ volatile unsigned g_gen;

// ---------------------------------------------------------------------------
// GEMM: A[16384][K] * W[3072][K]^T + bias -> g_xg  (scatter [dir][t*32+b][g])
// 128x128 block tile, BK=8, 8x8 microtile (split 64-halves: conflict-free LDS)
// ---------------------------------------------------------------------------
__global__ __launch_bounds__(256, 2) void gemm_xg(
    const float* __restrict__ Ap,     // nullptr -> g_xin
    const float* __restrict__ W,      // [3072][K]
    const float* __restrict__ bias,   // [3072]
    int K)
{
    const float* A = Ap ? Ap : g_xin;
    __shared__ float As[8][128];
    __shared__ float Bs[8][128];

    const int tid = threadIdx.x;
    const int bn = blockIdx.x;        // 0..23
    const int bm = blockIdx.y;        // 0..127
    const int lr = tid >> 1;          // 0..127
    const int lk = (tid & 1) << 2;    // 0 or 4

    const float* Ag = A + (size_t)(bm * 128 + lr) * K + lk;
    const float* Wg = W + (size_t)(bn * 128 + lr) * K + lk;

    float4 av = *(const float4*)Ag;
    float4 bv = *(const float4*)Wg;

    const int tx = tid & 15;
    const int ty = tid >> 4;

    float acc[8][8];
#pragma unroll
    for (int i = 0; i < 8; i++)
#pragma unroll
        for (int j = 0; j < 8; j++) acc[i][j] = 0.f;

    for (int kt = 0; kt < K; kt += 8) {
        As[lk + 0][lr] = av.x; As[lk + 1][lr] = av.y;
        As[lk + 2][lr] = av.z; As[lk + 3][lr] = av.w;
        Bs[lk + 0][lr] = bv.x; Bs[lk + 1][lr] = bv.y;
        Bs[lk + 2][lr] = bv.z; Bs[lk + 3][lr] = bv.w;
        __syncthreads();

        if (kt + 8 < K) {
            av = *(const float4*)(Ag + kt + 8);
            bv = *(const float4*)(Wg + kt + 8);
        }

#pragma unroll
        for (int k = 0; k < 8; k++) {
            float ar[8], br[8];
            *(float4*)&ar[0] = *(const float4*)&As[k][ty * 4];
            *(float4*)&ar[4] = *(const float4*)&As[k][64 + ty * 4];
            *(float4*)&br[0] = *(const float4*)&Bs[k][tx * 4];
            *(float4*)&br[4] = *(const float4*)&Bs[k][64 + tx * 4];
#pragma unroll
            for (int i = 0; i < 8; i++)
#pragma unroll
                for (int j = 0; j < 8; j++) acc[i][j] += ar[i] * br[j];
        }
        __syncthreads();
    }

    // Epilogue: + bias, scatter to xg[dir][t*32+b][g]
    const int n0a = bn * 128 + tx * 4;
    const int n0b = n0a + 64;
    const int dir = (bn >= 12);                    // tile never crosses dir
    const int g0a = n0a - dir * 1536;
    const int g0b = n0b - dir * 1536;
    float4 ba = *(const float4*)(bias + n0a);
    float4 bb = *(const float4*)(bias + n0b);
    float* xg = g_xg + dir * XG_DIR;

#pragma unroll
    for (int i = 0; i < 8; i++) {
        int mi = bm * 128 + ((i < 4) ? (ty * 4 + i) : (64 + ty * 4 + i - 4));
        int b = mi >> 9;
        int t = mi & 511;
        float* row = xg + (t * 32 + b) * 1536;
        float4 v;
        v.x = acc[i][0] + ba.x; v.y = acc[i][1] + ba.y;
        v.z = acc[i][2] + ba.z; v.w = acc[i][3] + ba.w;
        *(float4*)(row + g0a) = v;
        v.x = acc[i][4] + bb.x; v.y = acc[i][5] + bb.y;
        v.z = acc[i][6] + bb.z; v.w = acc[i][7] + bb.w;
        *(float4*)(row + g0b) = v;
    }
}

// ---------------------------------------------------------------------------
// Recurrence. 128 CTAs x 256 threads. CTA = (dir, 8 h-columns).
// smem: Ws[24][512] (3 gates x 8 cols of W_hh) + Hs[32][516] (padded h_prev,
//       conflict-free float4) + Bh[24] + Red[4*32*6]
// Thread = (k-half, col-pair, batch): 6 dot products of length 256.
// ---------------------------------------------------------------------------
#define REC_SMEM_FLOATS (12288 + 16512 + 32 + 768)
#define REC_SMEM_BYTES  (REC_SMEM_FLOATS * 4)

__global__ __launch_bounds__(256, 1) void gru_rec(
    const float* __restrict__ whh,    // [2][1536][512]
    const float* __restrict__ bhh)    // [2][1536]
{
    extern __shared__ float sm[];
    float* Ws  = sm;                       // [24][512]
    float* Hs  = sm + 12288;               // [32][516]
    float* Bh  = sm + 12288 + 16512;       // [24] (+pad)
    float* Red = Bh + 32;                  // [4][32][6]

    const int tid = threadIdx.x;
    const int dir = blockIdx.x >> 6;
    const int cb  = blockIdx.x & 63;

    // Load W_hh slice (gates r/z/n of our 8 columns), coalesced float4
    const float* wbase = whh + dir * (1536 * 512);
#pragma unroll
    for (int i = 0; i < 12; i++) {
        int idx = (tid + i * 256) << 2;     // 0..12287
        int row = idx >> 9;                 // g*8 + cl
        int k   = idx & 511;
        int g = row >> 3, cl = row & 7;
        float4 v = *(const float4*)(wbase + ((g << 9) + cb * 8 + cl) * 512 + k);
        *(float4*)(Ws + (row << 9) + k) = v;
    }
    if (tid < 24) {
        int g = tid >> 3, cl = tid & 7;
        Bh[tid] = bhh[dir * 1536 + (g << 9) + cb * 8 + cl];
    }
    __syncthreads();

    const int half = tid >> 7;              // k-split half
    const int rem  = tid & 127;
    const int cp   = rem >> 5;              // col pair 0..3
    const int b    = rem & 31;              // batch
    const int k0   = half << 8;             // 0 or 256
    const int c0   = cb * 8 + cp * 2;       // global h-column of first col

    const float* xgb = g_xg + dir * XG_DIR;
    float*       yb  = g_y  + dir * Y_DIR;

    const float* hrow = Hs + b * 516 + k0;
    const float* wr0  = Ws + (cp * 2 + 0) * 512 + k0;
    const float* wr1  = Ws + (cp * 2 + 1) * 512 + k0;

    const float bhr0 = Bh[cp * 2],      bhr1 = Bh[cp * 2 + 1];
    const float bhz0 = Bh[8 + cp * 2],  bhz1 = Bh[8 + cp * 2 + 1];
    const float bhn0 = Bh[16 + cp * 2], bhn1 = Bh[16 + cp * 2 + 1];

    for (int step = 0; step < 512; step++) {
        const int tt = dir ? (511 - step) : step;

        // Prefetch xg (hidden under staging + dot products)
        float xr0 = 0.f, xr1 = 0.f, xz0 = 0.f, xz1 = 0.f, xn0 = 0.f, xn1 = 0.f;
        if (half == 0) {
            const float* xp = xgb + (tt * 32 + b) * 1536 + c0;
            xr0 = __ldg(xp);        xr1 = __ldg(xp + 1);
            xz0 = __ldg(xp + 512);  xz1 = __ldg(xp + 513);
            xn0 = __ldg(xp + 1024); xn1 = __ldg(xp + 1025);
        }

        // Stage h_prev into Hs[b][k] (row stride 516)
        if (step == 0) {
            for (int i = tid; i < 32 * 516; i += 256) Hs[i] = 0.f;
        } else {
            const int tp = dir ? (tt + 1) : (tt - 1);
            const float* hp = yb + tp * (32 * 512);
#pragma unroll
            for (int i = 0; i < 16; i++) {
                int idx = (tid + i * 256) << 2;     // 0..16383
                int bb = idx >> 9, kk = idx & 511;
                *(float4*)(Hs + bb * 516 + kk) = *(const float4*)(hp + idx);
            }
        }
        __syncthreads();

        // 6 dot products over this thread's k-half
        float a00 = 0.f, a01 = 0.f, a10 = 0.f, a11 = 0.f, a20 = 0.f, a21 = 0.f;
#pragma unroll 4
        for (int k = 0; k < 256; k += 4) {
            float4 h4 = *(const float4*)(hrow + k);
            float4 w;
            w = *(const float4*)(wr0 + k);
            a00 += h4.x * w.x + h4.y * w.y + h4.z * w.z + h4.w * w.w;
            w = *(const float4*)(wr1 + k);
            a01 += h4.x * w.x + h4.y * w.y + h4.z * w.z + h4.w * w.w;
            w = *(const float4*)(wr0 + 4096 + k);          // z gate
            a10 += h4.x * w.x + h4.y * w.y + h4.z * w.z + h4.w * w.w;
            w = *(const float4*)(wr1 + 4096 + k);
            a11 += h4.x * w.x + h4.y * w.y + h4.z * w.z + h4.w * w.w;
            w = *(const float4*)(wr0 + 8192 + k);          // n gate
            a20 += h4.x * w.x + h4.y * w.y + h4.z * w.z + h4.w * w.w;
            w = *(const float4*)(wr1 + 8192 + k);
            a21 += h4.x * w.x + h4.y * w.y + h4.z * w.z + h4.w * w.w;
        }

        if (half) {
            float* r = Red + (cp * 32 + b) * 6;
            r[0] = a00; r[1] = a01; r[2] = a10; r[3] = a11; r[4] = a20; r[5] = a21;
        }
        __syncthreads();

        if (!half) {
            const float* r = Red + (cp * 32 + b) * 6;
            a00 += r[0]; a01 += r[1]; a10 += r[2];
            a11 += r[3]; a20 += r[4]; a21 += r[5];

            const float hp0 = Hs[b * 516 + c0];
            const float hp1 = Hs[b * 516 + c0 + 1];

            const float r0 = 1.f / (1.f + expf(-(xr0 + a00 + bhr0)));
            const float z0 = 1.f / (1.f + expf(-(xz0 + a10 + bhz0)));
            const float n0 = tanhf(xn0 + r0 * (a20 + bhn0));
            const float h0 = (1.f - z0) * n0 + z0 * hp0;

            const float r1 = 1.f / (1.f + expf(-(xr1 + a01 + bhr1)));
            const float z1 = 1.f / (1.f + expf(-(xz1 + a11 + bhz1)));
            const float n1 = tanhf(xn1 + r1 * (a21 + bhn1));
            const float h1 = (1.f - z1) * n1 + z1 * hp1;

            float* yo = yb + (tt * 32 + b) * 512 + c0;
            *(float2*)yo = make_float2(h0, h1);
            __threadfence();                 // push h writes GPU-visible
        }

        // ---- grid barrier (sense-reversal; all 128 CTAs co-resident) ----
        __syncthreads();
        if (tid == 0) {
            __threadfence();
            unsigned gen = g_gen;
            if (atomicAdd(&g_cnt, 1u) == 127u) {
                atomicExch(&g_cnt, 0u);
                __threadfence();
                g_gen = gen + 1u;            // release
            } else {
                while (g_gen == gen) { }     // volatile spin
            }
            __threadfence();
        }
        __syncthreads();
    }
}

// ---------------------------------------------------------------------------
// BatchNorm (training-mode batch stats), folded to scale/shift
// ---------------------------------------------------------------------------
__global__ void bn_zero()
{
    int i = threadIdx.x;                      // 1024 threads
    g_sum[i] = 0.f;
    g_sqs[i] = 0.f;
}

__global__ __launch_bounds__(256) void bn_stats()
{
    // 512 blocks: dir (2) x 64-row chunks (256). Coalesced column reads.
    const int dir   = blockIdx.x >> 8;
    const int chunk = blockIdx.x & 255;
    const float* p = g_y + dir * Y_DIR + chunk * 64 * 512;
    const int c0 = threadIdx.x, c1 = threadIdx.x + 256;
    float s0 = 0.f, q0 = 0.f, s1 = 0.f, q1 = 0.f;
#pragma unroll 4
    for (int r = 0; r < 64; r++) {
        float v0 = p[r * 512 + c0];
        float v1 = p[r * 512 + c1];
        s0 += v0; q0 += v0 * v0;
        s1 += v1; q1 += v1 * v1;
    }
    atomicAdd(&g_sum[dir * 512 + c0], s0);
    atomicAdd(&g_sqs[dir * 512 + c0], q0);
    atomicAdd(&g_sum[dir * 512 + c1], s1);
    atomicAdd(&g_sqs[dir * 512 + c1], q1);
}

__global__ void bn_finalize(const float* __restrict__ gamma,
                            const float* __restrict__ beta)
{
    int c = threadIdx.x;                      // 1024 threads
    float mean = g_sum[c] * (1.f / 16384.f);
    float var  = g_sqs[c] * (1.f / 16384.f) - mean * mean;
    float sc   = gamma[c] * rsqrtf(var + 1e-5f);
    g_scale[c] = sc;
    g_shift[c] = beta[c] - mean * sc;
}

__global__ __launch_bounds__(256) void bn_apply(float* __restrict__ out, int last)
{
    const int m = blockIdx.x;                 // b*512 + t
    const int t = m & 511, b = m >> 9;
    const int c = threadIdx.x * 4;            // channel 0..1023
    const int dir = c >> 9, hc = c & 511;
    float4 v  = *(const float4*)(g_y + dir * Y_DIR + (t * 32 + b) * 512 + hc);
    float4 sc = *(const float4*)(g_scale + c);
    float4 sh = *(const float4*)(g_shift + c);
    float4 o;
    o.x = v.x * sc.x + sh.x;
    o.y = v.y * sc.y + sh.y;
    o.z = v.z * sc.z + sh.z;
    o.w = v.w * sc.w + sh.w;
    float* dst = last ? out : g_xin;
    *(float4*)(dst + (size_t)m * 1024 + c) = o;
}

// ---------------------------------------------------------------------------
extern "C" void kernel_launch(void* const* d_in, const int* in_sizes, int n_in,
                              void* d_out, int out_size)
{
    const float* x         = (const float*)d_in[0];   // [32][512][1280]
    const float* w_ih0     = (const float*)d_in[1];   // [2][1536][1280]
    const float* w_hh0     = (const float*)d_in[2];   // [2][1536][512]
    const float* b_ih0     = (const float*)d_in[3];   // [2][1536]
    const float* b_hh0     = (const float*)d_in[4];   // [2][1536]
    const float* w_ih_rest = (const float*)d_in[5];   // [2][2][1536][1024]
    const float* w_hh_rest = (const float*)d_in[6];   // [2][2][1536][512]
    const float* b_ih_rest = (const float*)d_in[7];   // [2][2][1536]
    const float* b_hh_rest = (const float*)d_in[8];   // [2][2][1536]
    const float* gamma     = (const float*)d_in[9];   // [3][1024]
    const float* beta      = (const float*)d_in[10];  // [3][1024]
    float* out = (float*)d_out;                       // [32][512][1024]

    static int smem_set = 0;
    if (!smem_set) {
        cudaFuncSetAttribute(gru_rec, cudaFuncAttributeMaxDynamicSharedMemorySize,
                             REC_SMEM_BYTES);
        smem_set = 1;
    }

    for (int l = 0; l < 3; l++) {
        const float* A   = (l == 0) ? x : nullptr;    // nullptr -> g_xin
        const int    K   = (l == 0) ? 1280 : 1024;
        const float* Wih = (l == 0) ? w_ih0 : w_ih_rest + (size_t)(l - 1) * 2 * 1536 * 1024;
        const float* Bih = (l == 0) ? b_ih0 : b_ih_rest + (l - 1) * 3072;
        const float* Whh = (l == 0) ? w_hh0 : w_hh_rest + (size_t)(l - 1) * 2 * 1536 * 512;
        const float* Bhh = (l == 0) ? b_hh0 : b_hh_rest + (l - 1) * 3072;

        gemm_xg<<<dim3(24, 128), 256>>>(A, Wih, Bih, K);
        gru_rec<<<128, 256, REC_SMEM_BYTES>>>(Whh, Bhh);
        bn_zero<<<1, 1024>>>();
        bn_stats<<<512, 256>>>();
        bn_finalize<<<1, 1024>>>(gamma + l * 1024, beta + l * 1024);
        bn_apply<<<16384, 256>>>(out, (l == 2) ? 1 : 0);
    }
}

// round 6
// speedup vs baseline: 1.0393x; 1.0393x over previous
#include <cuda_runtime.h>
#include <math.h>

// B=32, T=512, F=1280, H=512, L=3. 3H=1536, 2H=1024. M=B*T=16384.
//
// Per layer l:
//   gemm_xg : xg[dir][t*32+b][1536] = in[b*512+t][:] . w_ih[dir*1536+g][:] + b_ih
//             (packed fma.rn.f32x2 inner loop, duplicated-A smem layout)
//   gru_rec : persistent, 128 CTAs (64/dir), 512 steps, per-direction grid barrier,
//             packed f32x2 dot products
//   bn_*    : training-mode batch stats folded to scale/shift, fused apply+transpose

#define XG_DIR 25165824   // 512*32*1536
#define Y_DIR   8388608   // 512*32*512

typedef unsigned long long u64;

#define FFMA2(c, a, b) asm("fma.rn.f32x2 %0, %1, %2, %0;" : "+l"(c) : "l"(a), "l"(b))

__device__ __forceinline__ float f2lo(u64 v) { return __uint_as_float((unsigned)v); }
__device__ __forceinline__ float f2hi(u64 v) { return __uint_as_float((unsigned)(v >> 32)); }

// ---------------- scratch (device globals; no allocation allowed) ----------
__device__ float g_xg[2 * XG_DIR];        // 201 MB
__device__ float g_y [2 * Y_DIR];         //  67 MB
__device__ float g_xin[32 * 512 * 1024];  //  67 MB
__device__ float g_scale[1024];
__device__ float g_shift[1024];
__device__ float g_sum[1024];
__device__ float g_sqs[1024];
__device__ unsigned g_cnt2[2];
__device__ volatile unsigned g_gen2[2];

// ---------------------------------------------------------------------------
// GEMM: A[16384][K] * W[3072][K]^T + bias -> g_xg  (scatter [dir][t*32+b][g])
// 128x128 block tile, BK=8, 8x8 microtile computed as 8x4 packed f32x2.
// As2 holds each A value duplicated (pairs), so LDS.128 yields {a,a} packs.
// ---------------------------------------------------------------------------
__global__ __launch_bounds__(256, 2) void gemm_xg(
    const float* __restrict__ Ap,     // nullptr -> g_xin
    const float* __restrict__ W,      // [3072][K]
    const float* __restrict__ bias,   // [3072]
    int K)
{
    const float* A = Ap ? Ap : g_xin;
    __shared__ float As2[8][256];     // duplicated: As2[k][2m]=As2[k][2m+1]=A
    __shared__ float Bs[8][128];

    const int tid = threadIdx.x;
    const int bn = blockIdx.x;        // 0..23
    const int bm = blockIdx.y;        // 0..127
    const int lr = tid >> 1;          // 0..127
    const int lk = (tid & 1) << 2;    // 0 or 4

    const float* Ag = A + (size_t)(bm * 128 + lr) * K + lk;
    const float* Wg = W + (size_t)(bn * 128 + lr) * K + lk;

    float4 av = *(const float4*)Ag;
    float4 bv = *(const float4*)Wg;

    const int tx = tid & 15;
    const int ty = tid >> 4;

    u64 acc[8][4];
#pragma unroll
    for (int i = 0; i < 8; i++)
#pragma unroll
        for (int j = 0; j < 4; j++) acc[i][j] = 0ull;

    for (int kt = 0; kt < K; kt += 8) {
        *(float2*)&As2[lk + 0][2 * lr] = make_float2(av.x, av.x);
        *(float2*)&As2[lk + 1][2 * lr] = make_float2(av.y, av.y);
        *(float2*)&As2[lk + 2][2 * lr] = make_float2(av.z, av.z);
        *(float2*)&As2[lk + 3][2 * lr] = make_float2(av.w, av.w);
        Bs[lk + 0][lr] = bv.x; Bs[lk + 1][lr] = bv.y;
        Bs[lk + 2][lr] = bv.z; Bs[lk + 3][lr] = bv.w;
        __syncthreads();

        if (kt + 8 < K) {
            av = *(const float4*)(Ag + kt + 8);
            bv = *(const float4*)(Wg + kt + 8);
        }

#pragma unroll
        for (int k = 0; k < 8; k++) {
            ulonglong2 a01 = *(const ulonglong2*)&As2[k][8 * ty];        // rows 0,1
            ulonglong2 a23 = *(const ulonglong2*)&As2[k][8 * ty + 4];    // rows 2,3
            ulonglong2 a45 = *(const ulonglong2*)&As2[k][128 + 8 * ty];  // rows 4,5
            ulonglong2 a67 = *(const ulonglong2*)&As2[k][128 + 8 * ty + 4];
            ulonglong2 b03 = *(const ulonglong2*)&Bs[k][tx * 4];         // cols 0-3
            ulonglong2 b47 = *(const ulonglong2*)&Bs[k][64 + tx * 4];    // cols 4-7

            FFMA2(acc[0][0], a01.x, b03.x); FFMA2(acc[0][1], a01.x, b03.y);
            FFMA2(acc[0][2], a01.x, b47.x); FFMA2(acc[0][3], a01.x, b47.y);
            FFMA2(acc[1][0], a01.y, b03.x); FFMA2(acc[1][1], a01.y, b03.y);
            FFMA2(acc[1][2], a01.y, b47.x); FFMA2(acc[1][3], a01.y, b47.y);
            FFMA2(acc[2][0], a23.x, b03.x); FFMA2(acc[2][1], a23.x, b03.y);
            FFMA2(acc[2][2], a23.x, b47.x); FFMA2(acc[2][3], a23.x, b47.y);
            FFMA2(acc[3][0], a23.y, b03.x); FFMA2(acc[3][1], a23.y, b03.y);
            FFMA2(acc[3][2], a23.y, b47.x); FFMA2(acc[3][3], a23.y, b47.y);
            FFMA2(acc[4][0], a45.x, b03.x); FFMA2(acc[4][1], a45.x, b03.y);
            FFMA2(acc[4][2], a45.x, b47.x); FFMA2(acc[4][3], a45.x, b47.y);
            FFMA2(acc[5][0], a45.y, b03.x); FFMA2(acc[5][1], a45.y, b03.y);
            FFMA2(acc[5][2], a45.y, b47.x); FFMA2(acc[5][3], a45.y, b47.y);
            FFMA2(acc[6][0], a67.x, b03.x); FFMA2(acc[6][1], a67.x, b03.y);
            FFMA2(acc[6][2], a67.x, b47.x); FFMA2(acc[6][3], a67.x, b47.y);
            FFMA2(acc[7][0], a67.y, b03.x); FFMA2(acc[7][1], a67.y, b03.y);
            FFMA2(acc[7][2], a67.y, b47.x); FFMA2(acc[7][3], a67.y, b47.y);
        }
        __syncthreads();
    }

    // Epilogue: + bias, scatter to xg[dir][t*32+b][g]
    const int n0a = bn * 128 + tx * 4;
    const int n0b = n0a + 64;
    const int dir = (bn >= 12);                    // tile never crosses dir
    const int g0a = n0a - dir * 1536;
    const int g0b = n0b - dir * 1536;
    float4 ba = *(const float4*)(bias + n0a);
    float4 bb = *(const float4*)(bias + n0b);
    float* xg = g_xg + dir * XG_DIR;

#pragma unroll
    for (int i = 0; i < 8; i++) {
        int mi = bm * 128 + ((i < 4) ? (ty * 4 + i) : (64 + ty * 4 + i - 4));
        int b = mi >> 9;
        int t = mi & 511;
        float* row = xg + (t * 32 + b) * 1536;
        float4 v;
        v.x = f2lo(acc[i][0]) + ba.x; v.y = f2hi(acc[i][0]) + ba.y;
        v.z = f2lo(acc[i][1]) + ba.z; v.w = f2hi(acc[i][1]) + ba.w;
        *(float4*)(row + g0a) = v;
        v.x = f2lo(acc[i][2]) + bb.x; v.y = f2hi(acc[i][2]) + bb.y;
        v.z = f2lo(acc[i][3]) + bb.z; v.w = f2hi(acc[i][3]) + bb.w;
        *(float4*)(row + g0b) = v;
    }
}

// ---------------------------------------------------------------------------
// Recurrence. 128 CTAs x 256 threads. CTA = (dir, 8 h-columns).
// smem: Ws[24][512] + Hs[32][516] (padded, conflict-free f4) + Bh + Red
// Thread = (k-half, col-pair, batch): 6 packed dot products of length 256.
// ---------------------------------------------------------------------------
#define REC_SMEM_FLOATS (12288 + 16512 + 32 + 768)
#define REC_SMEM_BYTES  (REC_SMEM_FLOATS * 4)

__global__ __launch_bounds__(256, 1) void gru_rec(
    const float* __restrict__ whh,    // [2][1536][512]
    const float* __restrict__ bhh)    // [2][1536]
{
    extern __shared__ float sm[];
    float* Ws  = sm;                       // [24][512]
    float* Hs  = sm + 12288;               // [32][516]
    float* Bh  = sm + 12288 + 16512;       // [24] (+pad)
    float* Red = Bh + 32;                  // [4][32][6]

    const int tid = threadIdx.x;
    const int dir = blockIdx.x >> 6;
    const int cb  = blockIdx.x & 63;

    // Load W_hh slice (gates r/z/n of our 8 columns), coalesced float4
    const float* wbase = whh + dir * (1536 * 512);
#pragma unroll
    for (int i = 0; i < 12; i++) {
        int idx = (tid + i * 256) << 2;     // 0..12287
        int row = idx >> 9;                 // g*8 + cl
        int k   = idx & 511;
        int g = row >> 3, cl = row & 7;
        float4 v = *(const float4*)(wbase + ((g << 9) + cb * 8 + cl) * 512 + k);
        *(float4*)(Ws + (row << 9) + k) = v;
    }
    if (tid < 24) {
        int g = tid >> 3, cl = tid & 7;
        Bh[tid] = bhh[dir * 1536 + (g << 9) + cb * 8 + cl];
    }
    __syncthreads();

    const int half = tid >> 7;              // k-split half
    const int rem  = tid & 127;
    const int cp   = rem >> 5;              // col pair 0..3
    const int b    = rem & 31;              // batch
    const int k0   = half << 8;             // 0 or 256
    const int c0   = cb * 8 + cp * 2;       // global h-column of first col

    const float* xgb = g_xg + dir * XG_DIR;
    float*       yb  = g_y  + dir * Y_DIR;

    const float* hrow = Hs + b * 516 + k0;
    const float* wr0  = Ws + (cp * 2 + 0) * 512 + k0;
    const float* wr1  = Ws + (cp * 2 + 1) * 512 + k0;

    const float bhr0 = Bh[cp * 2],      bhr1 = Bh[cp * 2 + 1];
    const float bhz0 = Bh[8 + cp * 2],  bhz1 = Bh[8 + cp * 2 + 1];
    const float bhn0 = Bh[16 + cp * 2], bhn1 = Bh[16 + cp * 2 + 1];

    for (int step = 0; step < 512; step++) {
        const int tt = dir ? (511 - step) : step;

        // Prefetch xg (hidden under staging + dot products)
        float xr0 = 0.f, xr1 = 0.f, xz0 = 0.f, xz1 = 0.f, xn0 = 0.f, xn1 = 0.f;
        if (half == 0) {
            const float* xp = xgb + (tt * 32 + b) * 1536 + c0;
            xr0 = __ldg(xp);        xr1 = __ldg(xp + 1);
            xz0 = __ldg(xp + 512);  xz1 = __ldg(xp + 513);
            xn0 = __ldg(xp + 1024); xn1 = __ldg(xp + 1025);
        }

        // Stage h_prev into Hs[b][k] (row stride 516)
        if (step == 0) {
            for (int i = tid; i < 32 * 516; i += 256) Hs[i] = 0.f;
        } else {
            const int tp = dir ? (tt + 1) : (tt - 1);
            const float* hp = yb + tp * (32 * 512);
#pragma unroll
            for (int i = 0; i < 16; i++) {
                int idx = (tid + i * 256) << 2;     // 0..16383
                int bb = idx >> 9, kk = idx & 511;
                *(float4*)(Hs + bb * 516 + kk) = *(const float4*)(hp + idx);
            }
        }
        __syncthreads();

        // 6 packed dot products over this thread's k-half
        u64 p00 = 0ull, p01 = 0ull, p10 = 0ull, p11 = 0ull, p20 = 0ull, p21 = 0ull;
#pragma unroll 4
        for (int k = 0; k < 256; k += 4) {
            ulonglong2 h2 = *(const ulonglong2*)(hrow + k);
            ulonglong2 w;
            w = *(const ulonglong2*)(wr0 + k);
            FFMA2(p00, h2.x, w.x); FFMA2(p00, h2.y, w.y);
            w = *(const ulonglong2*)(wr1 + k);
            FFMA2(p01, h2.x, w.x); FFMA2(p01, h2.y, w.y);
            w = *(const ulonglong2*)(wr0 + 4096 + k);          // z gate
            FFMA2(p10, h2.x, w.x); FFMA2(p10, h2.y, w.y);
            w = *(const ulonglong2*)(wr1 + 4096 + k);
            FFMA2(p11, h2.x, w.x); FFMA2(p11, h2.y, w.y);
            w = *(const ulonglong2*)(wr0 + 8192 + k);          // n gate
            FFMA2(p20, h2.x, w.x); FFMA2(p20, h2.y, w.y);
            w = *(const ulonglong2*)(wr1 + 8192 + k);
            FFMA2(p21, h2.x, w.x); FFMA2(p21, h2.y, w.y);
        }
        float a00 = f2lo(p00) + f2hi(p00);
        float a01 = f2lo(p01) + f2hi(p01);
        float a10 = f2lo(p10) + f2hi(p10);
        float a11 = f2lo(p11) + f2hi(p11);
        float a20 = f2lo(p20) + f2hi(p20);
        float a21 = f2lo(p21) + f2hi(p21);

        if (half) {
            float* r = Red + (cp * 32 + b) * 6;
            r[0] = a00; r[1] = a01; r[2] = a10; r[3] = a11; r[4] = a20; r[5] = a21;
        }
        __syncthreads();

        if (!half) {
            const float* r = Red + (cp * 32 + b) * 6;
            a00 += r[0]; a01 += r[1]; a10 += r[2];
            a11 += r[3]; a20 += r[4]; a21 += r[5];

            const float hp0 = Hs[b * 516 + c0];
            const float hp1 = Hs[b * 516 + c0 + 1];

            const float r0 = 1.f / (1.f + expf(-(xr0 + a00 + bhr0)));
            const float z0 = 1.f / (1.f + expf(-(xz0 + a10 + bhz0)));
            const float n0 = tanhf(xn0 + r0 * (a20 + bhn0));
            const float h0 = (1.f - z0) * n0 + z0 * hp0;

            const float r1 = 1.f / (1.f + expf(-(xr1 + a01 + bhr1)));
            const float z1 = 1.f / (1.f + expf(-(xz1 + a11 + bhz1)));
            const float n1 = tanhf(xn1 + r1 * (a21 + bhn1));
            const float h1 = (1.f - z1) * n1 + z1 * hp1;

            float* yo = yb + (tt * 32 + b) * 512 + c0;
            *(float2*)yo = make_float2(h0, h1);
        }

        // ---- per-direction grid barrier (sense-reversal; 64 CTAs/dir) ----
        __syncthreads();                     // all CTA stores done
        if (tid == 0) {
            __threadfence();                 // cumulative release
            unsigned gen = g_gen2[dir];
            if (atomicAdd(&g_cnt2[dir], 1u) == 63u) {
                atomicExch(&g_cnt2[dir], 0u);
                __threadfence();
                g_gen2[dir] = gen + 1u;      // release
            } else {
                while (g_gen2[dir] == gen) { }   // volatile spin (L1-bypass)
            }
            __threadfence();                 // acquire
        }
        __syncthreads();
    }
}

// ---------------------------------------------------------------------------
// BatchNorm (training-mode batch stats), folded to scale/shift
// ---------------------------------------------------------------------------
__global__ void bn_zero()
{
    int i = threadIdx.x;                      // 1024 threads
    g_sum[i] = 0.f;
    g_sqs[i] = 0.f;
}

__global__ __launch_bounds__(256) void bn_stats()
{
    // 512 blocks: dir (2) x 64-row chunks (256). Coalesced column reads.
    const int dir   = blockIdx.x >> 8;
    const int chunk = blockIdx.x & 255;
    const float* p = g_y + dir * Y_DIR + chunk * 64 * 512;
    const int c0 = threadIdx.x, c1 = threadIdx.x + 256;
    float s0 = 0.f, q0 = 0.f, s1 = 0.f, q1 = 0.f;
#pragma unroll 4
    for (int r = 0; r < 64; r++) {
        float v0 = p[r * 512 + c0];
        float v1 = p[r * 512 + c1];
        s0 += v0; q0 += v0 * v0;
        s1 += v1; q1 += v1 * v1;
    }
    atomicAdd(&g_sum[dir * 512 + c0], s0);
    atomicAdd(&g_sqs[dir * 512 + c0], q0);
    atomicAdd(&g_sum[dir * 512 + c1], s1);
    atomicAdd(&g_sqs[dir * 512 + c1], q1);
}

__global__ void bn_finalize(const float* __restrict__ gamma,
                            const float* __restrict__ beta)
{
    int c = threadIdx.x;                      // 1024 threads
    float mean = g_sum[c] * (1.f / 16384.f);
    float var  = g_sqs[c] * (1.f / 16384.f) - mean * mean;
    float sc   = gamma[c] * rsqrtf(var + 1e-5f);
    g_scale[c] = sc;
    g_shift[c] = beta[c] - mean * sc;
}

__global__ __launch_bounds__(256) void bn_apply(float* __restrict__ out, int last)
{
    const int m = blockIdx.x;                 // b*512 + t
    const int t = m & 511, b = m >> 9;
    const int c = threadIdx.x * 4;            // channel 0..1023
    const int dir = c >> 9, hc = c & 511;
    float4 v  = *(const float4*)(g_y + dir * Y_DIR + (t * 32 + b) * 512 + hc);
    float4 sc = *(const float4*)(g_scale + c);
    float4 sh = *(const float4*)(g_shift + c);
    float4 o;
    o.x = v.x * sc.x + sh.x;
    o.y = v.y * sc.y + sh.y;
    o.z = v.z * sc.z + sh.z;
    o.w = v.w * sc.w + sh.w;
    float* dst = last ? out : g_xin;
    *(float4*)(dst + (size_t)m * 1024 + c) = o;
}

// ---------------------------------------------------------------------------
extern "C" void kernel_launch(void* const* d_in, const int* in_sizes, int n_in,
                              void* d_out, int out_size)
{
    const float* x         = (const float*)d_in[0];   // [32][512][1280]
    const float* w_ih0     = (const float*)d_in[1];   // [2][1536][1280]
    const float* w_hh0     = (const float*)d_in[2];   // [2][1536][512]
    const float* b_ih0     = (const float*)d_in[3];   // [2][1536]
    const float* b_hh0     = (const float*)d_in[4];   // [2][1536]
    const float* w_ih_rest = (const float*)d_in[5];   // [2][2][1536][1024]
    const float* w_hh_rest = (const float*)d_in[6];   // [2][2][1536][512]
    const float* b_ih_rest = (const float*)d_in[7];   // [2][2][1536]
    const float* b_hh_rest = (const float*)d_in[8];   // [2][2][1536]
    const float* gamma     = (const float*)d_in[9];   // [3][1024]
    const float* beta      = (const float*)d_in[10];  // [3][1024]
    float* out = (float*)d_out;                       // [32][512][1024]

    static int smem_set = 0;
    if (!smem_set) {
        cudaFuncSetAttribute(gru_rec, cudaFuncAttributeMaxDynamicSharedMemorySize,
                             REC_SMEM_BYTES);
        smem_set = 1;
    }

    for (int l = 0; l < 3; l++) {
        const float* A   = (l == 0) ? x : nullptr;    // nullptr -> g_xin
        const int    K   = (l == 0) ? 1280 : 1024;
        const float* Wih = (l == 0) ? w_ih0 : w_ih_rest + (size_t)(l - 1) * 2 * 1536 * 1024;
        const float* Bih = (l == 0) ? b_ih0 : b_ih_rest + (l - 1) * 3072;
        const float* Whh = (l == 0) ? w_hh0 : w_hh_rest + (size_t)(l - 1) * 2 * 1536 * 512;
        const float* Bhh = (l == 0) ? b_hh0 : b_hh_rest + (l - 1) * 3072;

        gemm_xg<<<dim3(24, 128), 256>>>(A, Wih, Bih, K);
        gru_rec<<<128, 256, REC_SMEM_BYTES>>>(Whh, Bhh);
        bn_zero<<<1, 1024>>>();
        bn_stats<<<512, 256>>>();
        bn_finalize<<<1, 1024>>>(gamma + l * 1024, beta + l * 1024);
        bn_apply<<<16384, 256>>>(out, (l == 2) ? 1 : 0);
    }
}

// round 7
// speedup vs baseline: 1.2185x; 1.1724x over previous
#include <cuda_runtime.h>
#include <math.h>

// B=32, T=512, F=1280, H=512, L=3. 3H=1536, 2H=1024. M=B*T=16384.
//
// Layouts:
//   xg   [dir][t*32+b][1536]        (input projections, gate-major r/z/n)
//   y    [dir][t][c][b] (512x512x32) transposed hidden outputs
//   xin  [b*512+t][1024]            next-layer input / final output layout

#define XG_DIR 25165824   // 512*32*1536
#define Y_DIR   8388608   // 512*512*32

typedef unsigned long long u64;

#define FFMA2(c, a, b) asm("fma.rn.f32x2 %0, %1, %2, %0;" : "+l"(c) : "l"(a), "l"(b))

__device__ __forceinline__ u64 pk(float x) {
    u64 r; unsigned u = __float_as_uint(x);
    asm("mov.b64 %0, {%1, %1};" : "=l"(r) : "r"(u));
    return r;
}
__device__ __forceinline__ float f2lo(u64 v) { return __uint_as_float((unsigned)v); }
__device__ __forceinline__ float f2hi(u64 v) { return __uint_as_float((unsigned)(v >> 32)); }

// ---------------- scratch (device globals; no allocation allowed) ----------
__device__ float g_xg[2 * XG_DIR];        // 201 MB
__device__ float g_y [2 * Y_DIR];         //  67 MB
__device__ float g_xin[32 * 512 * 1024];  //  67 MB
__device__ float g_scale[1024];
__device__ float g_shift[1024];
__device__ float g_sum[1024];
__device__ float g_sqs[1024];
__device__ unsigned g_cnt2[2];
__device__ volatile unsigned g_gen2[2];

// ---------------------------------------------------------------------------
// GEMM: A[16384][K] * W[3072][K]^T + bias -> g_xg  (scatter [dir][t*32+b][g])
// 128(M) x 256(N) block tile, BK=8. Thread: 8 rows x 16 cols (8 f32x2 pairs).
// Crossbar: 6 LDS.128 per k per warp vs 64 FFMA2 -> FMA-bound.
// ---------------------------------------------------------------------------
__global__ __launch_bounds__(256) void gemm_xg(
    const float* __restrict__ Ap,     // nullptr -> g_xin
    const float* __restrict__ W,      // [3072][K]
    const float* __restrict__ bias,   // [3072]
    int K)
{
    const float* A = Ap ? Ap : g_xin;
    __shared__ float As[8][128];
    __shared__ float Bs[8][256];

    const int tid = threadIdx.x;
    const int bn = blockIdx.x;        // 0..11  (256-col tiles; 6 per direction)
    const int bm = blockIdx.y;        // 0..127
    const int lr = tid >> 1;          // 0..127 (A row)
    const int lk = (tid & 1) << 2;    // 0 or 4 (A k-offset)

    const float* Ag = A + (size_t)(bm * 128 + lr) * K + lk;
    const float* Wg = W + (size_t)(bn * 256 + tid) * K;

    float4 av  = *(const float4*)Ag;
    float4 bv0 = *(const float4*)Wg;
    float4 bv1 = *(const float4*)(Wg + 4);

    const int tx = tid & 15;
    const int ty = tid >> 4;

    u64 acc[8][8];
#pragma unroll
    for (int i = 0; i < 8; i++)
#pragma unroll
        for (int j = 0; j < 8; j++) acc[i][j] = 0ull;

    for (int kt = 0; kt < K; kt += 8) {
        As[lk + 0][lr] = av.x; As[lk + 1][lr] = av.y;
        As[lk + 2][lr] = av.z; As[lk + 3][lr] = av.w;
        Bs[0][tid] = bv0.x; Bs[1][tid] = bv0.y; Bs[2][tid] = bv0.z; Bs[3][tid] = bv0.w;
        Bs[4][tid] = bv1.x; Bs[5][tid] = bv1.y; Bs[6][tid] = bv1.z; Bs[7][tid] = bv1.w;
        __syncthreads();

        if (kt + 8 < K) {
            av  = *(const float4*)(Ag + kt + 8);
            bv0 = *(const float4*)(Wg + kt + 8);
            bv1 = *(const float4*)(Wg + kt + 12);
        }

#pragma unroll
        for (int k = 0; k < 8; k++) {
            float4 a0 = *(const float4*)&As[k][4 * ty];
            float4 a1 = *(const float4*)&As[k][64 + 4 * ty];
            u64 ap0 = pk(a0.x), ap1 = pk(a0.y), ap2 = pk(a0.z), ap3 = pk(a0.w);
            u64 ap4 = pk(a1.x), ap5 = pk(a1.y), ap6 = pk(a1.z), ap7 = pk(a1.w);
            ulonglong2 bq0 = *(const ulonglong2*)&Bs[k][4 * tx];
            ulonglong2 bq1 = *(const ulonglong2*)&Bs[k][64 + 4 * tx];
            ulonglong2 bq2 = *(const ulonglong2*)&Bs[k][128 + 4 * tx];
            ulonglong2 bq3 = *(const ulonglong2*)&Bs[k][192 + 4 * tx];
#define ROWFMA(i, ap)                                                   \
            FFMA2(acc[i][0], ap, bq0.x); FFMA2(acc[i][1], ap, bq0.y);   \
            FFMA2(acc[i][2], ap, bq1.x); FFMA2(acc[i][3], ap, bq1.y);   \
            FFMA2(acc[i][4], ap, bq2.x); FFMA2(acc[i][5], ap, bq2.y);   \
            FFMA2(acc[i][6], ap, bq3.x); FFMA2(acc[i][7], ap, bq3.y);
            ROWFMA(0, ap0) ROWFMA(1, ap1) ROWFMA(2, ap2) ROWFMA(3, ap3)
            ROWFMA(4, ap4) ROWFMA(5, ap5) ROWFMA(6, ap6) ROWFMA(7, ap7)
#undef ROWFMA
        }
        __syncthreads();
    }

    // Epilogue: + bias, scatter to xg[dir][t*32+b][g]
    const int nb  = bn * 256;
    const int dir = (bn >= 6);
    const int gb  = nb - dir * 1536 + 4 * tx;
    float4 bq[4];
#pragma unroll
    for (int q = 0; q < 4; q++)
        bq[q] = *(const float4*)(bias + nb + 64 * q + 4 * tx);
    float* xg = g_xg + dir * XG_DIR;

#pragma unroll
    for (int i = 0; i < 8; i++) {
        int row = (i < 4) ? (4 * ty + i) : (64 + 4 * ty + (i - 4));
        int m = bm * 128 + row;
        int b = m >> 9, t = m & 511;
        float* rp = xg + (t * 32 + b) * 1536 + gb;
#pragma unroll
        for (int q = 0; q < 4; q++) {
            float4 v;
            v.x = f2lo(acc[i][2 * q])     + bq[q].x;
            v.y = f2hi(acc[i][2 * q])     + bq[q].y;
            v.z = f2lo(acc[i][2 * q + 1]) + bq[q].z;
            v.w = f2hi(acc[i][2 * q + 1]) + bq[q].w;
            *(float4*)(rp + 64 * q) = v;
        }
    }
}

// ---------------------------------------------------------------------------
// Recurrence. 128 CTAs x 256 threads. CTA = (dir, 8 h-columns).
// Phase 1: thread (ks,cp,bg) = k-eighth, col-pair, batch-quad:
//          6 rows x 4 batches register tile, weights reused across 4 batches.
// Phase 2: thread (c2=warp, b2=lane): reduce 8 k-partials, gates, store h.
// smem: Ws[24][512] + Hs[512][32] (transposed h_prev) + Red[3][8][8][32] + Bh
// ---------------------------------------------------------------------------
#define REC_SMEM_FLOATS (12288 + 16384 + 6144 + 32)
#define REC_SMEM_BYTES  (REC_SMEM_FLOATS * 4)

__global__ __launch_bounds__(256, 1) void gru_rec(
    const float* __restrict__ whh,    // [2][1536][512]
    const float* __restrict__ bhh)    // [2][1536]
{
    extern __shared__ float sm[];
    float* Ws  = sm;                  // [24][512]
    float* Hs  = sm + 12288;          // [512][32]  h_prev, k-major
    float* Red = sm + 28672;          // [3][8][8][32] = (g, c, ks, b)
    float* Bh  = sm + 34816;          // [24]

    const int tid = threadIdx.x;
    const int dir = blockIdx.x >> 6;
    const int cb  = blockIdx.x & 63;

    const float* wbase = whh + dir * (1536 * 512);
#pragma unroll
    for (int i = 0; i < 12; i++) {
        int idx = (tid + i * 256) << 2;     // 0..12287
        int row = idx >> 9;                 // g*8 + cl
        int k   = idx & 511;
        int g = row >> 3, cl = row & 7;
        *(float4*)(Ws + (row << 9) + k) =
            *(const float4*)(wbase + ((g << 9) + cb * 8 + cl) * 512 + k);
    }
    if (tid < 24) {
        int g = tid >> 3, cl = tid & 7;
        Bh[tid] = bhh[dir * 1536 + (g << 9) + cb * 8 + cl];
    }
    __syncthreads();

    const int ks = tid >> 5;            // 0..7: k-eighth (phase1) == c2 (phase2)
    const int cp = (tid >> 3) & 3;      // col pair
    const int bg = tid & 7;             // batch quad
    const int b2 = tid & 31;            // phase-2 batch
    const int k0 = ks << 6;

    const float* xgb = g_xg + dir * XG_DIR;
    float*       yb  = g_y  + dir * Y_DIR;

    const float* hb = Hs + (k0 << 5) + (bg << 2);   // Hs[k0][4*bg]
    const float* wb = Ws + (cp << 1) * 512 + k0;    // row 2cp (g=0,j=0)
    const float bhr = Bh[ks], bhz = Bh[8 + ks], bhn = Bh[16 + ks];

    for (int step = 0; step < 512; step++) {
        const int tt = dir ? (511 - step) : step;

        // xg prefetch for phase 2 (hidden under staging + dots)
        const float* xp = xgb + (tt * 32 + b2) * 1536 + cb * 8 + ks;
        const float xr = __ldg(xp), xz = __ldg(xp + 512), xn = __ldg(xp + 1024);

        // stage h_prev into Hs[k][b]
        if (step == 0) {
#pragma unroll
            for (int i = 0; i < 16; i++)
                *(float4*)(Hs + ((tid + i * 256) << 2)) = make_float4(0.f, 0.f, 0.f, 0.f);
        } else {
            const int tp = dir ? (tt + 1) : (tt - 1);
            const float* src = yb + tp * 16384;
#pragma unroll
            for (int i = 0; i < 16; i++) {
                int idx = (tid + i * 256) << 2;
                *(float4*)(Hs + idx) = *(const float4*)(src + idx);
            }
        }
        __syncthreads();

        // phase 1: 6 rows x 2 batch-pairs over 64 k
        u64 acc[3][2][2];
#pragma unroll
        for (int g = 0; g < 3; g++)
#pragma unroll
            for (int j = 0; j < 2; j++) { acc[g][j][0] = 0ull; acc[g][j][1] = 0ull; }

#pragma unroll 4
        for (int kk = 0; kk < 64; kk += 4) {
            const float* hk = hb + (kk << 5);
            ulonglong2 h0 = *(const ulonglong2*)(hk);
            ulonglong2 h1 = *(const ulonglong2*)(hk + 32);
            ulonglong2 h2 = *(const ulonglong2*)(hk + 64);
            ulonglong2 h3 = *(const ulonglong2*)(hk + 96);
            const float* wk = wb + kk;
#pragma unroll
            for (int g = 0; g < 3; g++)
#pragma unroll
                for (int j = 0; j < 2; j++) {
                    float4 w = *(const float4*)(wk + g * 4096 + j * 512);
                    u64 p0 = pk(w.x), p1 = pk(w.y), p2 = pk(w.z), p3 = pk(w.w);
                    FFMA2(acc[g][j][0], h0.x, p0); FFMA2(acc[g][j][1], h0.y, p0);
                    FFMA2(acc[g][j][0], h1.x, p1); FFMA2(acc[g][j][1], h1.y, p1);
                    FFMA2(acc[g][j][0], h2.x, p2); FFMA2(acc[g][j][1], h2.y, p2);
                    FFMA2(acc[g][j][0], h3.x, p3); FFMA2(acc[g][j][1], h3.y, p3);
                }
        }

        // store partials: Red[(g*8 + 2cp+j)*256 + ks*32 + 4bg + {0,2}]
#pragma unroll
        for (int g = 0; g < 3; g++)
#pragma unroll
            for (int j = 0; j < 2; j++) {
                float* rp = Red + (((g << 3) + (cp << 1) + j) << 8) + (ks << 5) + (bg << 2);
                *(u64*)(rp)     = acc[g][j][0];
                *(u64*)(rp + 2) = acc[g][j][1];
            }
        __syncthreads();

        // phase 2: thread (c2=ks, b2) reduces and applies gates
        {
            float s[3];
#pragma unroll
            for (int g = 0; g < 3; g++) {
                const float* rp = Red + (((g << 3) + ks) << 8) + b2;
                float t0 = rp[0]   + rp[32],  t1 = rp[64]  + rp[96];
                float t2 = rp[128] + rp[160], t3 = rp[192] + rp[224];
                s[g] = (t0 + t1) + (t2 + t3);
            }
            const float hp = Hs[(((cb << 3) + ks) << 5) + b2];
            const float r = 1.f / (1.f + expf(-(xr + s[0] + bhr)));
            const float z = 1.f / (1.f + expf(-(xz + s[1] + bhz)));
            const float n = tanhf(xn + r * (s[2] + bhn));
            yb[tt * 16384 + (((cb << 3) + ks) << 5) + b2] = (1.f - z) * n + z * hp;
        }

        // per-direction grid barrier (sense-reversal; 64 co-resident CTAs)
        __syncthreads();
        if (tid == 0) {
            __threadfence();
            unsigned gen = g_gen2[dir];
            if (atomicAdd(&g_cnt2[dir], 1u) == 63u) {
                atomicExch(&g_cnt2[dir], 0u);
                __threadfence();
                g_gen2[dir] = gen + 1u;
            } else {
                while (g_gen2[dir] == gen) { }
            }
            __threadfence();
        }
        __syncthreads();
    }
}

// ---------------------------------------------------------------------------
// BatchNorm (training-mode batch stats), folded to scale/shift
// ---------------------------------------------------------------------------
__global__ void bn_zero()
{
    int i = threadIdx.x;                      // 1024 threads
    g_sum[i] = 0.f;
    g_sqs[i] = 0.f;
}

__global__ __launch_bounds__(256) void bn_stats()
{
    // 1024 blocks = channels. y[dir][t][c][b]: warp reads 32 b (coalesced).
    const int ch = blockIdx.x;
    const int dir = ch >> 9, c = ch & 511;
    const float* p = g_y + dir * Y_DIR + c * 32;
    float s = 0.f, q = 0.f;
#pragma unroll 4
    for (int i = threadIdx.x; i < 512 * 32; i += 256) {
        int t = i >> 5, b = i & 31;
        float v = p[t * 16384 + b];
        s += v; q += v * v;
    }
#pragma unroll
    for (int o = 16; o > 0; o >>= 1) {
        s += __shfl_down_sync(0xFFFFFFFFu, s, o);
        q += __shfl_down_sync(0xFFFFFFFFu, q, o);
    }
    if ((threadIdx.x & 31) == 0) {
        atomicAdd(&g_sum[ch], s);
        atomicAdd(&g_sqs[ch], q);
    }
}

__global__ void bn_finalize(const float* __restrict__ gamma,
                            const float* __restrict__ beta)
{
    int c = threadIdx.x;                      // 1024 threads
    float mean = g_sum[c] * (1.f / 16384.f);
    float var  = g_sqs[c] * (1.f / 16384.f) - mean * mean;
    float sc   = gamma[c] * rsqrtf(var + 1e-5f);
    g_scale[c] = sc;
    g_shift[c] = beta[c] - mean * sc;
}

// bn_apply with smem tile transpose: y[dir][t][c][b] -> out[b*512+t][ch]
__global__ __launch_bounds__(256) void bn_apply(float* __restrict__ out, int last)
{
    __shared__ float tile[256 * 33];
    const int bi   = blockIdx.x;              // t(512) x dir(2) x half(2)
    const int t    = bi >> 2;
    const int dir  = (bi >> 1) & 1;
    const int half = bi & 1;

    const float* src = g_y + dir * Y_DIR + t * 16384 + half * 256 * 32;
    // load: lanes over b (coalesced), rows over c
    for (int i = threadIdx.x; i < 8192; i += 256) {
        int c = i >> 5, b = i & 31;
        tile[c * 33 + b] = src[c * 32 + b];
    }
    __syncthreads();

    float* dst = last ? out : g_xin;
    const int chb = dir * 512 + half * 256;
    // write: lanes over c (coalesced out + scale/shift)
    for (int i = threadIdx.x; i < 8192; i += 256) {
        int b = i >> 8, c = i & 255;
        int ch = chb + c;
        dst[(size_t)(b * 512 + t) * 1024 + ch] =
            tile[c * 33 + b] * g_scale[ch] + g_shift[ch];
    }
}

// ---------------------------------------------------------------------------
extern "C" void kernel_launch(void* const* d_in, const int* in_sizes, int n_in,
                              void* d_out, int out_size)
{
    const float* x         = (const float*)d_in[0];   // [32][512][1280]
    const float* w_ih0     = (const float*)d_in[1];   // [2][1536][1280]
    const float* w_hh0     = (const float*)d_in[2];   // [2][1536][512]
    const float* b_ih0     = (const float*)d_in[3];   // [2][1536]
    const float* b_hh0     = (const float*)d_in[4];   // [2][1536]
    const float* w_ih_rest = (const float*)d_in[5];   // [2][2][1536][1024]
    const float* w_hh_rest = (const float*)d_in[6];   // [2][2][1536][512]
    const float* b_ih_rest = (const float*)d_in[7];   // [2][2][1536]
    const float* b_hh_rest = (const float*)d_in[8];   // [2][2][1536]
    const float* gamma     = (const float*)d_in[9];   // [3][1024]
    const float* beta      = (const float*)d_in[10];  // [3][1024]
    float* out = (float*)d_out;                       // [32][512][1024]

    static int smem_set = 0;
    if (!smem_set) {
        cudaFuncSetAttribute(gru_rec, cudaFuncAttributeMaxDynamicSharedMemorySize,
                             REC_SMEM_BYTES);
        smem_set = 1;
    }

    for (int l = 0; l < 3; l++) {
        const float* A   = (l == 0) ? x : nullptr;    // nullptr -> g_xin
        const int    K   = (l == 0) ? 1280 : 1024;
        const float* Wih = (l == 0) ? w_ih0 : w_ih_rest + (size_t)(l - 1) * 2 * 1536 * 1024;
        const float* Bih = (l == 0) ? b_ih0 : b_ih_rest + (l - 1) * 3072;
        const float* Whh = (l == 0) ? w_hh0 : w_hh_rest + (size_t)(l - 1) * 2 * 1536 * 512;
        const float* Bhh = (l == 0) ? b_hh0 : b_hh_rest + (l - 1) * 3072;

        gemm_xg<<<dim3(12, 128), 256>>>(A, Wih, Bih, K);
        gru_rec<<<128, 256, REC_SMEM_BYTES>>>(Whh, Bhh);
        bn_zero<<<1, 1024>>>();
        bn_stats<<<1024, 256>>>();
        bn_finalize<<<1, 1024>>>(gamma + l * 1024, beta + l * 1024);
        bn_apply<<<2048, 256>>>(out, (l == 2) ? 1 : 0);
    }
}

// round 8
// speedup vs baseline: 1.2239x; 1.0045x over previous
#include <cuda_runtime.h>
#include <math.h>

// B=32, T=512, F=1280, H=512, L=3. 3H=1536, 2H=1024. M=B*T=16384.
//
// Layouts:
//   xg   [dir][t*32+b][1536]        (input projections, gate-major r/z/n)
//   y    [dir][t][c][b] (512x512x32) transposed hidden outputs
//   xin  [b*512+t][1024]            next-layer input / final output layout

#define XG_DIR 25165824   // 512*32*1536
#define Y_DIR   8388608   // 512*512*32

typedef unsigned long long u64;

#define FFMA2(c, a, b) asm("fma.rn.f32x2 %0, %1, %2, %0;" : "+l"(c) : "l"(a), "l"(b))

__device__ __forceinline__ u64 pk(float x) {
    u64 r; unsigned u = __float_as_uint(x);
    asm("mov.b64 %0, {%1, %1};" : "=l"(r) : "r"(u));
    return r;
}
__device__ __forceinline__ u64 pk2(float a, float b) {
    u64 r;
    asm("mov.b64 %0, {%1, %2};" : "=l"(r)
        : "r"(__float_as_uint(a)), "r"(__float_as_uint(b)));
    return r;
}
__device__ __forceinline__ float f2lo(u64 v) { return __uint_as_float((unsigned)v); }
__device__ __forceinline__ float f2hi(u64 v) { return __uint_as_float((unsigned)(v >> 32)); }

// ---------------- scratch (device globals; no allocation allowed) ----------
__device__ float g_xg[2 * XG_DIR];        // 201 MB
__device__ float g_y [2 * Y_DIR];         //  67 MB
__device__ float g_xin[32 * 512 * 1024];  //  67 MB
__device__ float g_scale[1024];
__device__ float g_shift[1024];
__device__ float g_sum[1024];
__device__ float g_sqs[1024];
__device__ volatile unsigned g_flag[2][64];   // per-CTA arrival counters
__device__ volatile unsigned g_rel[2];        // release counters

// ---------------------------------------------------------------------------
// GEMM: A[16384][K] * W[3072][K]^T + bias -> g_xg  (scatter [dir][t*32+b][g])
// 128(M) x 256(N) block tile, BK=8. Thread: 8 rows x 16 cols (8 f32x2 pairs).
// ---------------------------------------------------------------------------
__global__ __launch_bounds__(256) void gemm_xg(
    const float* __restrict__ Ap,     // nullptr -> g_xin
    const float* __restrict__ W,      // [3072][K]
    const float* __restrict__ bias,   // [3072]
    int K)
{
    const float* A = Ap ? Ap : g_xin;
    __shared__ float As[8][128];
    __shared__ float Bs[8][256];

    const int tid = threadIdx.x;
    const int bn = blockIdx.x;        // 0..11  (256-col tiles; 6 per direction)
    const int bm = blockIdx.y;        // 0..127
    const int lr = tid >> 1;          // 0..127 (A row)
    const int lk = (tid & 1) << 2;    // 0 or 4 (A k-offset)

    const float* Ag = A + (size_t)(bm * 128 + lr) * K + lk;
    const float* Wg = W + (size_t)(bn * 256 + tid) * K;

    float4 av  = *(const float4*)Ag;
    float4 bv0 = *(const float4*)Wg;
    float4 bv1 = *(const float4*)(Wg + 4);

    const int tx = tid & 15;
    const int ty = tid >> 4;

    u64 acc[8][8];
#pragma unroll
    for (int i = 0; i < 8; i++)
#pragma unroll
        for (int j = 0; j < 8; j++) acc[i][j] = 0ull;

    for (int kt = 0; kt < K; kt += 8) {
        As[lk + 0][lr] = av.x; As[lk + 1][lr] = av.y;
        As[lk + 2][lr] = av.z; As[lk + 3][lr] = av.w;
        Bs[0][tid] = bv0.x; Bs[1][tid] = bv0.y; Bs[2][tid] = bv0.z; Bs[3][tid] = bv0.w;
        Bs[4][tid] = bv1.x; Bs[5][tid] = bv1.y; Bs[6][tid] = bv1.z; Bs[7][tid] = bv1.w;
        __syncthreads();

        if (kt + 8 < K) {
            av  = *(const float4*)(Ag + kt + 8);
            bv0 = *(const float4*)(Wg + kt + 8);
            bv1 = *(const float4*)(Wg + kt + 12);
        }

#pragma unroll
        for (int k = 0; k < 8; k++) {
            float4 a0 = *(const float4*)&As[k][4 * ty];
            float4 a1 = *(const float4*)&As[k][64 + 4 * ty];
            u64 ap0 = pk(a0.x), ap1 = pk(a0.y), ap2 = pk(a0.z), ap3 = pk(a0.w);
            u64 ap4 = pk(a1.x), ap5 = pk(a1.y), ap6 = pk(a1.z), ap7 = pk(a1.w);
            ulonglong2 bq0 = *(const ulonglong2*)&Bs[k][4 * tx];
            ulonglong2 bq1 = *(const ulonglong2*)&Bs[k][64 + 4 * tx];
            ulonglong2 bq2 = *(const ulonglong2*)&Bs[k][128 + 4 * tx];
            ulonglong2 bq3 = *(const ulonglong2*)&Bs[k][192 + 4 * tx];
#define ROWFMA(i, ap)                                                   \
            FFMA2(acc[i][0], ap, bq0.x); FFMA2(acc[i][1], ap, bq0.y);   \
            FFMA2(acc[i][2], ap, bq1.x); FFMA2(acc[i][3], ap, bq1.y);   \
            FFMA2(acc[i][4], ap, bq2.x); FFMA2(acc[i][5], ap, bq2.y);   \
            FFMA2(acc[i][6], ap, bq3.x); FFMA2(acc[i][7], ap, bq3.y);
            ROWFMA(0, ap0) ROWFMA(1, ap1) ROWFMA(2, ap2) ROWFMA(3, ap3)
            ROWFMA(4, ap4) ROWFMA(5, ap5) ROWFMA(6, ap6) ROWFMA(7, ap7)
#undef ROWFMA
        }
        __syncthreads();
    }

    // Epilogue: + bias, scatter to xg[dir][t*32+b][g]
    const int nb  = bn * 256;
    const int dir = (bn >= 6);
    const int gb  = nb - dir * 1536 + 4 * tx;
    float4 bq[4];
#pragma unroll
    for (int q = 0; q < 4; q++)
        bq[q] = *(const float4*)(bias + nb + 64 * q + 4 * tx);
    float* xg = g_xg + dir * XG_DIR;

#pragma unroll
    for (int i = 0; i < 8; i++) {
        int row = (i < 4) ? (4 * ty + i) : (64 + 4 * ty + (i - 4));
        int m = bm * 128 + row;
        int b = m >> 9, t = m & 511;
        float* rp = xg + (t * 32 + b) * 1536 + gb;
#pragma unroll
        for (int q = 0; q < 4; q++) {
            float4 v;
            v.x = f2lo(acc[i][2 * q])     + bq[q].x;
            v.y = f2hi(acc[i][2 * q])     + bq[q].y;
            v.z = f2lo(acc[i][2 * q + 1]) + bq[q].z;
            v.w = f2hi(acc[i][2 * q + 1]) + bq[q].w;
            *(float4*)(rp + 64 * q) = v;
        }
    }
}

// ---------------------------------------------------------------------------
// Recurrence. 128 CTAs x 256 threads. CTA = (dir, 8 h-columns).
// Phase 1: thread (ks,cp,bg): 6 rows x 4 batches, h_prev read directly from
//          g_y via __ldcg (L2-coherent, latency hidden under FFMA2).
// Phase 2: thread (c2=ks-warp, b2=lane): reduce 8 k-partials, gates, store h.
// Grid barrier: distributed arrival flags (plain stores) + master release.
// smem: Ws[24][512] + Red[24][264] + Bh[24]
// ---------------------------------------------------------------------------
#define REC_SMEM_FLOATS (12288 + 6336 + 32)
#define REC_SMEM_BYTES  (REC_SMEM_FLOATS * 4)

__global__ __launch_bounds__(256, 1) void gru_rec(
    const float* __restrict__ whh,    // [2][1536][512]
    const float* __restrict__ bhh)    // [2][1536]
{
    extern __shared__ float sm[];
    float* Ws  = sm;                  // [24][512]
    float* Red = sm + 12288;          // [24][264] = (g*8 + c, ks*32 + b) padded
    float* Bh  = sm + 12288 + 6336;   // [24]

    const int tid = threadIdx.x;
    const int dir = blockIdx.x >> 6;
    const int cb  = blockIdx.x & 63;

    const unsigned base = g_rel[dir];     // stable pre-barrier read (replay-safe)

    const float* wbase = whh + dir * (1536 * 512);
#pragma unroll
    for (int i = 0; i < 12; i++) {
        int idx = (tid + i * 256) << 2;     // 0..12287
        int row = idx >> 9;                 // g*8 + cl
        int k   = idx & 511;
        int g = row >> 3, cl = row & 7;
        *(float4*)(Ws + (row << 9) + k) =
            *(const float4*)(wbase + ((g << 9) + cb * 8 + cl) * 512 + k);
    }
    if (tid < 24) {
        int g = tid >> 3, cl = tid & 7;
        Bh[tid] = bhh[dir * 1536 + (g << 9) + cb * 8 + cl];
    }
    __syncthreads();

    const int ks = tid >> 5;            // 0..7: k-eighth (p1) == local col (p2)
    const int cp = (tid >> 3) & 3;      // col pair
    const int bg = tid & 7;             // batch quad
    const int b2 = tid & 31;            // phase-2 batch
    const int k0 = ks << 6;

    const float* xgb = g_xg + dir * XG_DIR;
    float*       yb  = g_y  + dir * Y_DIR;

    const float* wb = Ws + (cp << 1) * 512 + k0;    // row 2cp (g=0,j=0)
    const float bhr = Bh[ks], bhz = Bh[8 + ks], bhn = Bh[16 + ks];

    for (int step = 0; step < 512; step++) {
        const int tt = dir ? (511 - step) : step;
        const int tp = dir ? (tt + 1) : (tt - 1);
        const float* hsrc = yb + tp * 16384;        // prev y [512c][32b]

        // xg prefetch for phase 2 (hidden under phase 1)
        const float* xp = xgb + (tt * 32 + b2) * 1536 + cb * 8 + ks;
        const float xr = __ldg(xp), xz = __ldg(xp + 512), xn = __ldg(xp + 1024);

        // phase 1: 6 rows x 2 batch-pairs over 64 k, h from L2 (ldcg)
        u64 acc[3][2][2];
#pragma unroll
        for (int g = 0; g < 3; g++)
#pragma unroll
            for (int j = 0; j < 2; j++) { acc[g][j][0] = 0ull; acc[g][j][1] = 0ull; }

        if (step > 0) {
            const float* hg = hsrc + (k0 << 5) + (bg << 2);
#pragma unroll 4
            for (int kk = 0; kk < 64; kk += 4) {
                u64 ha[4][2];
#pragma unroll
                for (int q = 0; q < 4; q++) {
                    float4 f = __ldcg((const float4*)(hg + ((kk + q) << 5)));
                    ha[q][0] = pk2(f.x, f.y);
                    ha[q][1] = pk2(f.z, f.w);
                }
                const float* wk = wb + kk;
#pragma unroll
                for (int g = 0; g < 3; g++)
#pragma unroll
                    for (int j = 0; j < 2; j++) {
                        float4 w = *(const float4*)(wk + g * 4096 + j * 512);
                        u64 p0 = pk(w.x), p1 = pk(w.y), p2 = pk(w.z), p3 = pk(w.w);
                        FFMA2(acc[g][j][0], ha[0][0], p0); FFMA2(acc[g][j][1], ha[0][1], p0);
                        FFMA2(acc[g][j][0], ha[1][0], p1); FFMA2(acc[g][j][1], ha[1][1], p1);
                        FFMA2(acc[g][j][0], ha[2][0], p2); FFMA2(acc[g][j][1], ha[2][1], p2);
                        FFMA2(acc[g][j][0], ha[3][0], p3); FFMA2(acc[g][j][1], ha[3][1], p3);
                    }
            }
        }

        // store partials: Red[(g*8 + 2cp+j)][ks*32 + 4bg + {0,2}]  (stride 264)
#pragma unroll
        for (int g = 0; g < 3; g++)
#pragma unroll
            for (int j = 0; j < 2; j++) {
                float* rp = Red + ((g << 3) + (cp << 1) + j) * 264 + (ks << 5) + (bg << 2);
                *(u64*)(rp)     = acc[g][j][0];
                *(u64*)(rp + 2) = acc[g][j][1];
            }
        __syncthreads();

        // phase 2: thread (ks, b2) reduces and applies gates
        {
            float s[3];
#pragma unroll
            for (int g = 0; g < 3; g++) {
                const float* rp = Red + ((g << 3) + ks) * 264 + b2;
                float t0 = rp[0]   + rp[32],  t1 = rp[64]  + rp[96];
                float t2 = rp[128] + rp[160], t3 = rp[192] + rp[224];
                s[g] = (t0 + t1) + (t2 + t3);
            }
            const float hp = (step > 0)
                ? __ldcg(hsrc + (((cb << 3) + ks) << 5) + b2) : 0.f;
            const float r = 1.f / (1.f + expf(-(xr + s[0] + bhr)));
            const float z = 1.f / (1.f + expf(-(xz + s[1] + bhz)));
            const float n = tanhf(xn + r * (s[2] + bhn));
            yb[tt * 16384 + (((cb << 3) + ks) << 5) + b2] = (1.f - z) * n + z * hp;
        }

        // ---- distributed-flag grid barrier (per direction, 64 CTAs) ----
        __syncthreads();                         // all y stores issued
        const unsigned tgt = base + (unsigned)step + 1u;
        if (tid == 0) {
            __threadfence();                     // y visible before arrival
            g_flag[dir][cb] = tgt;               // plain volatile store
        }
        if (cb == 0) {
            if (tid < 64) {
                while ((int)(g_flag[dir][tid] - tgt) < 0) { }
            }
            __syncthreads();                     // all 64 arrivals observed
            if (tid == 0) {
                __threadfence();                 // cumulative release
                g_rel[dir] = tgt;
            }
            __syncthreads();
        } else {
            if (tid == 0) {
                while ((int)(g_rel[dir] - tgt) < 0) { }
                __threadfence();                 // acquire
            }
            __syncthreads();
        }
    }
}

// ---------------------------------------------------------------------------
// BatchNorm (training-mode batch stats), folded to scale/shift
// ---------------------------------------------------------------------------
__global__ void bn_zero()
{
    int i = threadIdx.x;                      // 1024 threads
    g_sum[i] = 0.f;
    g_sqs[i] = 0.f;
}

__global__ __launch_bounds__(256) void bn_stats()
{
    // 1024 blocks = channels. y[dir][t][c][b]: warp reads 32 b (coalesced).
    const int ch = blockIdx.x;
    const int dir = ch >> 9, c = ch & 511;
    const float* p = g_y + dir * Y_DIR + c * 32;
    float s = 0.f, q = 0.f;
#pragma unroll 4
    for (int i = threadIdx.x; i < 512 * 32; i += 256) {
        int t = i >> 5, b = i & 31;
        float v = p[t * 16384 + b];
        s += v; q += v * v;
    }
#pragma unroll
    for (int o = 16; o > 0; o >>= 1) {
        s += __shfl_down_sync(0xFFFFFFFFu, s, o);
        q += __shfl_down_sync(0xFFFFFFFFu, q, o);
    }
    if ((threadIdx.x & 31) == 0) {
        atomicAdd(&g_sum[ch], s);
        atomicAdd(&g_sqs[ch], q);
    }
}

__global__ void bn_finalize(const float* __restrict__ gamma,
                            const float* __restrict__ beta)
{
    int c = threadIdx.x;                      // 1024 threads
    float mean = g_sum[c] * (1.f / 16384.f);
    float var  = g_sqs[c] * (1.f / 16384.f) - mean * mean;
    float sc   = gamma[c] * rsqrtf(var + 1e-5f);
    g_scale[c] = sc;
    g_shift[c] = beta[c] - mean * sc;
}

// bn_apply with smem tile transpose: y[dir][t][c][b] -> out[b*512+t][ch]
__global__ __launch_bounds__(256) void bn_apply(float* __restrict__ out, int last)
{
    __shared__ float tile[256 * 33];
    const int bi   = blockIdx.x;              // t(512) x dir(2) x half(2)
    const int t    = bi >> 2;
    const int dir  = (bi >> 1) & 1;
    const int half = bi & 1;

    const float* src = g_y + dir * Y_DIR + t * 16384 + half * 256 * 32;
    for (int i = threadIdx.x; i < 8192; i += 256) {
        int c = i >> 5, b = i & 31;
        tile[c * 33 + b] = src[c * 32 + b];
    }
    __syncthreads();

    float* dst = last ? out : g_xin;
    const int chb = dir * 512 + half * 256;
    for (int i = threadIdx.x; i < 8192; i += 256) {
        int b = i >> 8, c = i & 255;
        int ch = chb + c;
        dst[(size_t)(b * 512 + t) * 1024 + ch] =
            tile[c * 33 + b] * g_scale[ch] + g_shift[ch];
    }
}

// ---------------------------------------------------------------------------
extern "C" void kernel_launch(void* const* d_in, const int* in_sizes, int n_in,
                              void* d_out, int out_size)
{
    const float* x         = (const float*)d_in[0];   // [32][512][1280]
    const float* w_ih0     = (const float*)d_in[1];   // [2][1536][1280]
    const float* w_hh0     = (const float*)d_in[2];   // [2][1536][512]
    const float* b_ih0     = (const float*)d_in[3];   // [2][1536]
    const float* b_hh0     = (const float*)d_in[4];   // [2][1536]
    const float* w_ih_rest = (const float*)d_in[5];   // [2][2][1536][1024]
    const float* w_hh_rest = (const float*)d_in[6];   // [2][2][1536][512]
    const float* b_ih_rest = (const float*)d_in[7];   // [2][2][1536]
    const float* b_hh_rest = (const float*)d_in[8];   // [2][2][1536]
    const float* gamma     = (const float*)d_in[9];   // [3][1024]
    const float* beta      = (const float*)d_in[10];  // [3][1024]
    float* out = (float*)d_out;                       // [32][512][1024]

    static int smem_set = 0;
    if (!smem_set) {
        cudaFuncSetAttribute(gru_rec, cudaFuncAttributeMaxDynamicSharedMemorySize,
                             REC_SMEM_BYTES);
        smem_set = 1;
    }

    for (int l = 0; l < 3; l++) {
        const float* A   = (l == 0) ? x : nullptr;    // nullptr -> g_xin
        const int    K   = (l == 0) ? 1280 : 1024;
        const float* Wih = (l == 0) ? w_ih0 : w_ih_rest + (size_t)(l - 1) * 2 * 1536 * 1024;
        const float* Bih = (l == 0) ? b_ih0 : b_ih_rest + (l - 1) * 3072;
        const float* Whh = (l == 0) ? w_hh0 : w_hh_rest + (size_t)(l - 1) * 2 * 1536 * 512;
        const float* Bhh = (l == 0) ? b_hh0 : b_hh_rest + (l - 1) * 3072;

        gemm_xg<<<dim3(12, 128), 256>>>(A, Wih, Bih, K);
        gru_rec<<<128, 256, REC_SMEM_BYTES>>>(Whh, Bhh);
        bn_zero<<<1, 1024>>>();
        bn_stats<<<1024, 256>>>();
        bn_finalize<<<1, 1024>>>(gamma + l * 1024, beta + l * 1024);
        bn_apply<<<2048, 256>>>(out, (l == 2) ? 1 : 0);
    }
}